// round 1
// baseline (speedup 1.0000x reference)
#include <cuda_runtime.h>
#include <math.h>
#include <stdint.h>

#define NN     20001
#define NREAL  20000
#define EPAD   1200000
#define RADIUS_F 0.1125f

// ---------------- scratch (device globals; no allocations) ----------------
__device__ float g_B[(size_t)NN * 64 * 96];        // bin accumulator, max cin=96
__device__ float g_bufA[(size_t)NN * 96];
__device__ float g_bufB[(size_t)NN * 96];
__device__ float g_inp[(size_t)NN * 96];
__device__ float g_y[(size_t)NN * 64];
__device__ float g_ww[(size_t)EPAD * 8];           // win * trilinear weight per corner
__device__ unsigned long long g_kfp[EPAD];         // 8 packed 6-bit kernel indices
__device__ int g_rowstart[NN + 2];
__device__ int g_Ereal;

// ---------------- helpers ----------------
__device__ __forceinline__ float fsign(float v) {
    return (v > 0.f) ? 1.f : ((v < 0.f) ? -1.f : 0.f);
}

__device__ __forceinline__ void ball_to_cube(float x, float y, float z,
                                             float& a, float& b, float& zc) {
    const float eps = 1e-9f;
    float sq   = x * x + y * y + z * z;
    float norm = sqrtf(sq + eps);
    float rxy2 = x * x + y * y;
    bool  polar = 1.25f * z * z > rxy2;
    float s = polar ? sqrtf(3.f * norm / (norm + fabsf(z) + eps))
                    : norm / sqrtf(rxy2 + eps);
    float xc = x * s;
    float yc = y * s;
    float zz = polar ? fsign(z) * norm : 1.5f * z;
    if (sq < 1e-12f) { xc = 0.f; yc = 0.f; zz = 0.f; }
    float r  = sqrtf(xc * xc + yc * yc + eps);
    bool  c1 = fabsf(xc) >= fabsf(yc);
    float xs = (fabsf(xc) < eps) ? eps : xc;
    float ys = (fabsf(yc) < eps) ? eps : yc;
    const float fop = 1.27323954473516268615f;  // 4/pi
    float av = c1 ? fsign(xc) * r : fsign(yc) * r * fop * atanf(xc / ys);
    float bv = c1 ? fsign(xc) * r * fop * atanf(yc / xs) : fsign(yc) * r;
    if (xc * xc + yc * yc < 1e-12f) { av = 0.f; bv = 0.f; }
    a = av; b = bv; zc = zz;
}

// ---------------- setup kernels ----------------
__global__ void k_init() { g_Ereal = EPAD; }

__global__ void k_findpad(const int* __restrict__ dst) {
    int e = blockIdx.x * blockDim.x + threadIdx.x;
    if (e >= EPAD) return;
    if (dst[e] >= NREAL) atomicMin(&g_Ereal, e);
}

__global__ void k_rowstart(const int* __restrict__ src) {
    int i = blockIdx.x * blockDim.x + threadIdx.x;
    if (i > NN) return;  // rows 0..NN (row[NN] = E_real sentinel not needed beyond 20001)
    int E = g_Ereal;
    int lo = 0, hi = E;
    while (lo < hi) {
        int mid = (lo + hi) >> 1;
        if (src[mid] < i) lo = mid + 1; else hi = mid;
    }
    g_rowstart[i] = lo;
}

__global__ void k_geom(const float* __restrict__ pos,
                       const int* __restrict__ src,
                       const int* __restrict__ dst) {
    int e = blockIdx.x * blockDim.x + threadIdx.x;
    if (e >= EPAD) return;
    int d = dst[e];
    if (d >= NREAL) return;  // pad edge (win == 0)
    int s = src[e];
    float ox = (pos[(size_t)d * 3 + 0] - pos[(size_t)s * 3 + 0]) * (1.f / RADIUS_F);
    float oy = (pos[(size_t)d * 3 + 1] - pos[(size_t)s * 3 + 1]) * (1.f / RADIUS_F);
    float oz = (pos[(size_t)d * 3 + 2] - pos[(size_t)s * 3 + 2]) * (1.f / RADIUS_F);
    float r2 = ox * ox + oy * oy + oz * oz;
    float u  = 1.f - r2;
    float win = u * u * u;
    win = fminf(fmaxf(win, 0.f), 1.f);
    float ca, cb, cc;
    ball_to_cube(ox, oy, oz, ca, cb, cc);
    float gx = fminf(fmaxf((ca * 0.5f + 0.5f) * 3.f, 0.f), 3.f);
    float gy = fminf(fmaxf((cb * 0.5f + 0.5f) * 3.f, 0.f), 3.f);
    float gz = fminf(fmaxf((cc * 0.5f + 0.5f) * 3.f, 0.f), 3.f);
    float fx = floorf(gx), fy = floorf(gy), fz = floorf(gz);
    float tx = gx - fx, ty = gy - fy, tz = gz - fz;
    int ix0 = min((int)fx, 3), ix1 = min((int)fx + 1, 3);
    int iy0 = min((int)fy, 3), iy1 = min((int)fy + 1, 3);
    int iz0 = min((int)fz, 3), iz1 = min((int)fz + 1, 3);
    unsigned long long kp = 0;
    #pragma unroll
    for (int c = 0; c < 8; c++) {
        int bx = (c >> 2) & 1, by = (c >> 1) & 1, bz = c & 1;
        int kf = ((bx ? ix1 : ix0) * 4 + (by ? iy1 : iy0)) * 4 + (bz ? iz1 : iz0);
        float w = (bx ? tx : 1.f - tx) * (by ? ty : 1.f - ty) * (bz ? tz : 1.f - tz);
        g_ww[(size_t)e * 8 + c] = w * win;
        kp |= (unsigned long long)kf << (8 * c);
    }
    g_kfp[e] = kp;
}

// ---------------- feature prep ----------------
__global__ void k_prep0(const float* __restrict__ feats, float* __restrict__ inp) {
    int i = blockIdx.x * blockDim.x + threadIdx.x;
    if (i >= NN * 13) return;
    int n = i / 13, c = i % 13;
    inp[i] = (c == 0) ? 1.0f : feats[(size_t)n * 12 + (c - 1)];
}

__global__ void k_relu(const float* __restrict__ x, float* __restrict__ inp, int total) {
    int i = blockIdx.x * blockDim.x + threadIdx.x;
    if (i < total) inp[i] = fmaxf(x[i], 0.f);
}

// ---------------- per-node scatter into shared bins ----------------
__global__ void k_scatter(const float* __restrict__ inp,
                          const int* __restrict__ dstArr, int cin) {
    __shared__ float Bl[64 * 96];
    int node = blockIdx.x;
    int tid  = threadIdx.x;  // 128
    int nk   = 64 * cin;
    for (int i = tid; i < nk; i += 128) Bl[i] = 0.f;
    __syncthreads();
    int e0 = g_rowstart[node], e1 = g_rowstart[node + 1];
    int warp = tid >> 5, lane = tid & 31;
    for (int e = e0 + warp; e < e1; e += 4) {
        int d = dstArr[e];
        unsigned long long kp = g_kfp[e];
        float w[8];
        #pragma unroll
        for (int j = 0; j < 8; j++) w[j] = g_ww[(size_t)e * 8 + j];
        for (int cc = 0; cc < cin; cc += 32) {
            int ch = cc + lane;
            if (ch < cin) {
                float fv = inp[(size_t)d * cin + ch];
                #pragma unroll
                for (int j = 0; j < 8; j++) {
                    int kf = (int)((kp >> (8 * j)) & 63ull);
                    atomicAdd(&Bl[kf * cin + ch], fv * w[j]);
                }
            }
        }
    }
    __syncthreads();
    float* Bg = g_B + (size_t)node * nk;
    for (int i = tid; i < nk; i += 128) Bg[i] = Bl[i];
}

// ---------------- fp32 SGEMM: C[M,ncols] = A[M,Kd] @ W[Kd,ncols] ----------------
__global__ void k_gemm(const float* __restrict__ A, const float* __restrict__ W,
                       float* __restrict__ C, int M, int Kd, int ncols) {
    __shared__ float As[16][64];
    __shared__ float Ws[16][64];
    int tid = threadIdx.x;      // 256
    int m0  = blockIdx.x * 64;
    int tx  = tid & 15, ty = tid >> 4;
    float acc[4][4];
    #pragma unroll
    for (int i = 0; i < 4; i++)
        #pragma unroll
        for (int j = 0; j < 4; j++) acc[i][j] = 0.f;

    int am = tid >> 2;              // 0..63
    int ak = (tid & 3) * 4;         // 0,4,8,12
    int wk = tid >> 4;              // 0..15
    int wn = (tid & 15) * 4;        // 0..60

    for (int k0 = 0; k0 < Kd; k0 += 16) {
        float4 av = make_float4(0.f, 0.f, 0.f, 0.f);
        if (m0 + am < M)
            av = *reinterpret_cast<const float4*>(A + (size_t)(m0 + am) * Kd + k0 + ak);
        As[ak + 0][am] = av.x; As[ak + 1][am] = av.y;
        As[ak + 2][am] = av.z; As[ak + 3][am] = av.w;

        if (ncols == 64) {
            float4 wv = *reinterpret_cast<const float4*>(W + (size_t)(k0 + wk) * 64 + wn);
            Ws[wk][wn + 0] = wv.x; Ws[wk][wn + 1] = wv.y;
            Ws[wk][wn + 2] = wv.z; Ws[wk][wn + 3] = wv.w;
        } else {
            #pragma unroll
            for (int j = 0; j < 4; j++) {
                int col = wn + j;
                Ws[wk][col] = (col < ncols) ? W[(size_t)(k0 + wk) * ncols + col] : 0.f;
            }
        }
        __syncthreads();
        #pragma unroll
        for (int kk = 0; kk < 16; kk++) {
            float4 a4 = *reinterpret_cast<const float4*>(&As[kk][ty * 4]);
            float4 b4 = *reinterpret_cast<const float4*>(&Ws[kk][tx * 4]);
            float aa[4] = {a4.x, a4.y, a4.z, a4.w};
            float bb[4] = {b4.x, b4.y, b4.z, b4.w};
            #pragma unroll
            for (int i = 0; i < 4; i++)
                #pragma unroll
                for (int j = 0; j < 4; j++)
                    acc[i][j] = fmaf(aa[i], bb[j], acc[i][j]);
        }
        __syncthreads();
    }
    #pragma unroll
    for (int i = 0; i < 4; i++) {
        int row = m0 + ty * 4 + i;
        if (row < M) {
            #pragma unroll
            for (int j = 0; j < 4; j++) {
                int col = tx * 4 + j;
                if (col < ncols) C[(size_t)row * ncols + col] = acc[i][j];
            }
        }
    }
}

// ---------------- epilogue: conv bias + dense path + residual ----------------
__global__ void k_combine(const float* __restrict__ y, const float* __restrict__ cb,
                          const float* __restrict__ dw, const float* __restrict__ db,
                          const float* __restrict__ inp, int cin,
                          const float* __restrict__ xold, int xold_stride,
                          float* __restrict__ out, int out_stride, int out_rows,
                          int conv_cols, int dense_cols, int dense_off, float scale) {
    __shared__ float si[96];
    int n = blockIdx.x;
    int o = threadIdx.x;  // 96
    if (o < cin) si[o] = inp[(size_t)n * cin + o];
    __syncthreads();
    int width = dense_off + dense_cols;
    if (conv_cols > width) width = conv_cols;
    if (o >= width || n >= out_rows) return;
    float v = 0.f;
    if (o < conv_cols) v = y[(size_t)n * conv_cols + o] + cb[o];
    if (o >= dense_off) {
        int od = o - dense_off;
        if (od < dense_cols) {
            float s2 = db[od];
            for (int i = 0; i < cin; i++) s2 = fmaf(si[i], dw[i * dense_cols + od], s2);
            v += s2;
        }
    }
    if (xold) v += xold[(size_t)n * xold_stride + o];
    out[(size_t)n * out_stride + o] = v * scale;
}

// ---------------- launch ----------------
extern "C" void kernel_launch(void* const* d_in, const int* in_sizes, int n_in,
                              void* d_out, int out_size) {
    const float* pos   = (const float*)d_in[0];
    const float* feats = (const float*)d_in[1];
    const int*   esrc  = (const int*)d_in[2];
    const int*   edst  = (const int*)d_in[3];
    const float* c0w = (const float*)d_in[4];
    const float* c0b = (const float*)d_in[5];
    const float* d0w = (const float*)d_in[6];
    const float* d0b = (const float*)d_in[7];
    const float* c1w = (const float*)d_in[8];
    const float* c1b = (const float*)d_in[9];
    const float* d1w = (const float*)d_in[10];
    const float* d1b = (const float*)d_in[11];
    const float* c2w = (const float*)d_in[12];
    const float* c2b = (const float*)d_in[13];
    const float* d2w = (const float*)d_in[14];
    const float* d2b = (const float*)d_in[15];
    const float* c3w = (const float*)d_in[16];
    const float* c3b = (const float*)d_in[17];
    const float* d3w = (const float*)d_in[18];
    const float* d3b = (const float*)d_in[19];
    float* out = (float*)d_out;

    void *pB, *pA, *pBB, *pI, *pY;
    cudaGetSymbolAddress(&pB,  g_B);
    cudaGetSymbolAddress(&pA,  g_bufA);
    cudaGetSymbolAddress(&pBB, g_bufB);
    cudaGetSymbolAddress(&pI,  g_inp);
    cudaGetSymbolAddress(&pY,  g_y);
    float* B    = (float*)pB;
    float* bufA = (float*)pA;
    float* bufB = (float*)pBB;
    float* inp  = (float*)pI;
    float* y    = (float*)pY;

    const int EB = (EPAD + 255) / 256;
    const int GT = (20001 + 63) / 64;  // 313 GEMM M-tiles

    // one-time-per-launch edge preprocessing (shared by all 4 conv layers)
    k_init<<<1, 1>>>();
    k_findpad<<<EB, 256>>>(edst);
    k_rowstart<<<(NN + 2 + 255) / 256, 256>>>(esrc);
    k_geom<<<EB, 256>>>(pos, esrc, edst);

    // ---- layer 0 ----
    k_prep0<<<(NN * 13 + 255) / 256, 256>>>(feats, inp);
    k_scatter<<<NN, 128>>>(inp, edst, 13);
    k_gemm<<<GT, 256>>>(B, c0w, y, NN, 64 * 13, 64);
    k_combine<<<NN, 96>>>(y, c0b, d0w, d0b, inp, 13, nullptr, 0,
                          bufA, 96, NN, 64, 32, 64, 1.f);
    // ---- layer 1 ----
    k_relu<<<(NN * 96 + 255) / 256, 256>>>(bufA, inp, NN * 96);
    k_scatter<<<NN, 128>>>(inp, edst, 96);
    k_gemm<<<GT, 256>>>(B, c1w, y, NN, 64 * 96, 64);
    k_combine<<<NN, 96>>>(y, c1b, d1w, d1b, inp, 96, nullptr, 0,
                          bufB, 64, NN, 64, 64, 0, 1.f);
    // ---- layer 2 (residual) ----
    k_relu<<<(NN * 64 + 255) / 256, 256>>>(bufB, inp, NN * 64);
    k_scatter<<<NN, 128>>>(inp, edst, 64);
    k_gemm<<<GT, 256>>>(B, c2w, y, NN, 64 * 64, 64);
    k_combine<<<NN, 96>>>(y, c2b, d2w, d2b, inp, 64, bufB, 64,
                          bufA, 64, NN, 64, 64, 0, 1.f);
    // ---- layer 3 (output, /128, first 20000 rows) ----
    k_relu<<<(NN * 64 + 255) / 256, 256>>>(bufA, inp, NN * 64);
    k_scatter<<<NN, 128>>>(inp, edst, 64);
    k_gemm<<<GT, 256>>>(B, c3w, y, NN, 64 * 64, 3);
    k_combine<<<NREAL, 96>>>(y, c3b, d3w, d3b, inp, 64, nullptr, 0,
                             out, 3, NREAL, 3, 3, 0, 1.f / 128.f);
}